// round 5
// baseline (speedup 1.0000x reference)
#include <cuda_runtime.h>
#include <cuda_bf16.h>
#include <math.h>
#include <stdint.h>

// ----------------------------------------------------------------------------
// TContrastive: GRACE InfoNCE, bf16 tensor-core (mma.sync m16n8k16) version.
// All GEMMs (projection + similarity) run on HMMA with fp32 accumulation.
// Similarity matrices are never materialized: exp + row/col/diag reductions
// fused into the mma epilogue using the documented fragment layout.
// ----------------------------------------------------------------------------

#define NS 8192
#define DD 1024
#define NTILE (NS / 128)          // 64
#define SMS 56                    // smem row stride in bf16 elems (112B)

typedef __nv_bfloat16 bf16;
typedef __nv_bfloat162 bf162;

// ---- static scratch (module-load allocation; no host API in kernel_launch) --
__device__ bf16 b_A1[NS*DD];
__device__ bf16 b_A2[NS*DD];
__device__ bf16 b_U1[NS*DD];
__device__ bf16 b_U2[NS*DD];
__device__ bf16 b_H1[NS*DD];
__device__ bf16 b_H2[NS*DD];
__device__ bf16 b_W1[DD*DD];
__device__ bf16 b_W2[DD*DD];
__device__ bf16 b_W3[DD*DD];
__device__ bf16 b_W4[DD*DD];
__device__ float g_r11[NS], g_r22[NS], g_r12[NS], g_c12[NS];
__device__ float g_d11[NS], g_d22[NS], g_d12[NS];
__device__ float g_loss[2];

// ---------------- mma helpers ------------------------------------------------
__device__ __forceinline__ void ldm_x4(uint32_t& r0, uint32_t& r1, uint32_t& r2,
                                       uint32_t& r3, const bf16* p)
{
    uint32_t a = (uint32_t)__cvta_generic_to_shared(p);
    asm volatile("ldmatrix.sync.aligned.m8n8.x4.shared.b16 {%0,%1,%2,%3}, [%4];"
                 : "=r"(r0), "=r"(r1), "=r"(r2), "=r"(r3) : "r"(a));
}

__device__ __forceinline__ void mma16816(float* c, const uint32_t* a, const uint32_t* b)
{
    asm volatile("mma.sync.aligned.m16n8k16.row.col.f32.bf16.bf16.f32 "
                 "{%0,%1,%2,%3}, {%4,%5,%6,%7}, {%8,%9}, {%0,%1,%2,%3};"
                 : "+f"(c[0]), "+f"(c[1]), "+f"(c[2]), "+f"(c[3])
                 : "r"(a[0]), "r"(a[1]), "r"(a[2]), "r"(a[3]),
                   "r"(b[0]), "r"(b[1]));
}

// Shared mainloop: computes 128x128 fp32 tile of A(m0..)·B(n0..)^T, K=1024.
// Warp grid 2x4: warp (wm, wn) owns rows wm*64.. cols wn*32..; acc[ti][tj][4].
// Thread element map (m16n8k16 C): c0,c1 -> row grp, cols qid*2,+1; c2,c3 -> row grp+8.
__device__ __forceinline__ void mma_mainloop(const bf16* __restrict__ A,
    const bf16* __restrict__ B, int m0, int n0,
    bf16* As, bf16* Bs, float acc[4][4][4])
{
    const int tid = threadIdx.x;
    const int lane = tid & 31;
    const int wid = tid >> 5;
    const int wm = wid >> 2, wn = wid & 3;
    const int r    = lane & 7;
    const int tsel = lane >> 3;
    // A-frag lane addressing: tile order (m0-7,k0-7),(m8-15,k0-7),(m0-7,k8-15),(m8-15,k8-15)
    const int a_row = ((tsel & 1) << 3) + r;
    const int a_col = (tsel >> 1) << 3;
    // B-frag lane addressing for x4 over 2 n-tiles:
    const int b_row = ((tsel >> 1) << 3) + r;
    const int b_col = ((tsel & 1) << 3);

    #pragma unroll
    for (int i = 0; i < 4; i++)
        #pragma unroll
        for (int j = 0; j < 4; j++)
            #pragma unroll
            for (int q = 0; q < 4; q++) acc[i][j][q] = 0.f;

    for (int kk = 0; kk < DD; kk += 32) {
        #pragma unroll
        for (int it = 0; it < 2; it++) {
            int id  = tid + it * 256;          // 0..511
            int row = id >> 2, q = id & 3;
            *(uint4*)&As[row*SMS + q*8] =
                *(const uint4*)(A + (size_t)(m0 + row) * DD + kk + q*8);
            *(uint4*)&Bs[row*SMS + q*8] =
                *(const uint4*)(B + (size_t)(n0 + row) * DD + kk + q*8);
        }
        __syncthreads();

        #pragma unroll
        for (int ks = 0; ks < 32; ks += 16) {
            uint32_t a[4][4], b[4][2];
            #pragma unroll
            for (int ti = 0; ti < 4; ti++) {
                const bf16* p = &As[(wm*64 + ti*16 + a_row)*SMS + ks + a_col];
                ldm_x4(a[ti][0], a[ti][1], a[ti][2], a[ti][3], p);
            }
            #pragma unroll
            for (int ppair = 0; ppair < 2; ppair++) {
                const bf16* p = &Bs[(wn*32 + ppair*16 + b_row)*SMS + ks + b_col];
                ldm_x4(b[2*ppair][0], b[2*ppair][1], b[2*ppair+1][0], b[2*ppair+1][1], p);
            }
            #pragma unroll
            for (int ti = 0; ti < 4; ti++)
                #pragma unroll
                for (int tj = 0; tj < 4; tj++)
                    mma16816(acc[ti][tj], a[ti], b[tj]);
        }
        __syncthreads();
    }
}

// ---------------- projection GEMM: C = [elu](A·W^T + bias), bf16 out --------
template<int MODE>
__device__ __forceinline__ void gemm_body(const bf16* __restrict__ A,
    const bf16* __restrict__ W, const float* __restrict__ bias,
    bf16* __restrict__ C)
{
    __shared__ bf16 As[128*SMS];
    __shared__ bf16 Bs[128*SMS];
    const int m0 = blockIdx.y * 128;
    const int n0 = blockIdx.x * 128;
    const int lane = threadIdx.x & 31;
    const int wid = threadIdx.x >> 5;
    const int wm = wid >> 2, wn = wid & 3;
    const int grp = lane >> 2, qid = lane & 3;

    float acc[4][4][4];
    mma_mainloop(A, W, m0, n0, As, Bs, acc);

    #pragma unroll
    for (int tj = 0; tj < 4; tj++) {
        int gc = n0 + wn*32 + tj*8 + qid*2;
        float bv0 = bias[gc], bv1 = bias[gc+1];
        #pragma unroll
        for (int ti = 0; ti < 4; ti++) {
            #pragma unroll
            for (int h = 0; h < 2; h++) {
                int gr = m0 + wm*64 + ti*16 + h*8 + grp;
                float v0 = acc[ti][tj][h*2+0] + bv0;
                float v1 = acc[ti][tj][h*2+1] + bv1;
                if (MODE == 1) {
                    v0 = v0 > 0.f ? v0 : expm1f(v0);
                    v1 = v1 > 0.f ? v1 : expm1f(v1);
                }
                *(bf162*)(C + (size_t)gr * DD + gc) = __floats2bfloat162_rn(v0, v1);
            }
        }
    }
}

__global__ __launch_bounds__(256) void g_A1W1U1(const float* bias)
{ gemm_body<1>(b_A1, b_W1, bias, b_U1); }
__global__ __launch_bounds__(256) void g_A2W1U2(const float* bias)
{ gemm_body<1>(b_A2, b_W1, bias, b_U2); }
__global__ __launch_bounds__(256) void g_U1W2H1(const float* bias)
{ gemm_body<0>(b_U1, b_W2, bias, b_H1); }
__global__ __launch_bounds__(256) void g_U2W2H2(const float* bias)
{ gemm_body<0>(b_U2, b_W2, bias, b_H2); }
__global__ __launch_bounds__(256) void g_A1W3U1(const float* bias)
{ gemm_body<1>(b_A1, b_W3, bias, b_U1); }
__global__ __launch_bounds__(256) void g_A2W3U2(const float* bias)
{ gemm_body<1>(b_A2, b_W3, bias, b_U2); }
__global__ __launch_bounds__(256) void g_U1W4H1(const float* bias)
{ gemm_body<0>(b_U1, b_W4, bias, b_H1); }
__global__ __launch_bounds__(256) void g_U2W4H2(const float* bias)
{ gemm_body<0>(b_U2, b_W4, bias, b_H2); }

// ---------------- fused exp-similarity + reductions -------------------------
// SYM: packed upper-tri grid (y=bi, bj=bi+x, exit if bj>=NTILE); off-diag
// tiles fold col sums into rs. FULL: rows->rs, cols->cs. Diag -> dg.
template<bool SYM>
__device__ __forceinline__ void sim_body(const bf16* __restrict__ A,
    const bf16* __restrict__ B, float* __restrict__ rs, float* __restrict__ cs,
    float* __restrict__ dg)
{
    const int bi = blockIdx.y;
    const int bj = SYM ? (bi + blockIdx.x) : blockIdx.x;
    if (SYM && bj >= NTILE) return;

    __shared__ bf16 As[128*SMS];
    __shared__ bf16 Bs[128*SMS];
    const int m0 = bi * 128;
    const int n0 = bj * 128;
    const int lane = threadIdx.x & 31;
    const int wid = threadIdx.x >> 5;
    const int wm = wid >> 2, wn = wid & 3;
    const int grp = lane >> 2, qid = lane & 3;
    const bool diag = (bi == bj);

    float acc[4][4][4];
    mma_mainloop(A, B, m0, n0, As, Bs, acc);

    // exp + row sums + diag
    #pragma unroll
    for (int ti = 0; ti < 4; ti++) {
        #pragma unroll
        for (int h = 0; h < 2; h++) {
            int gr = m0 + wm*64 + ti*16 + h*8 + grp;
            float rsum = 0.f;
            #pragma unroll
            for (int tj = 0; tj < 4; tj++) {
                int gc = n0 + wn*32 + tj*8 + qid*2;
                float e0 = __expf(2.f * acc[ti][tj][h*2+0]);
                float e1 = __expf(2.f * acc[ti][tj][h*2+1]);
                acc[ti][tj][h*2+0] = e0;
                acc[ti][tj][h*2+1] = e1;
                rsum += e0 + e1;
                if (diag) {
                    if (gr == gc)     dg[gr] = e0;
                    if (gr == gc + 1) dg[gr] = e1;
                }
            }
            rsum += __shfl_down_sync(0xffffffffu, rsum, 2, 4);
            rsum += __shfl_down_sync(0xffffffffu, rsum, 1, 4);
            if (qid == 0) atomicAdd(&rs[gr], rsum);
        }
    }

    // col sums
    const bool doCols = (!SYM) || (bj > bi);
    if (doCols) {
        float* csOut = SYM ? rs : cs;
        #pragma unroll
        for (int tj = 0; tj < 4; tj++) {
            float c0 = 0.f, c1 = 0.f;
            #pragma unroll
            for (int ti = 0; ti < 4; ti++) {
                c0 += acc[ti][tj][0] + acc[ti][tj][2];
                c1 += acc[ti][tj][1] + acc[ti][tj][3];
            }
            // reduce over the 8 lane-groups (lanes differing in bits 2..4)
            #pragma unroll
            for (int o = 4; o <= 16; o <<= 1) {
                c0 += __shfl_xor_sync(0xffffffffu, c0, o);
                c1 += __shfl_xor_sync(0xffffffffu, c1, o);
            }
            if (grp == 0) {
                int gc = n0 + wn*32 + tj*8 + qid*2;
                atomicAdd(&csOut[gc],   c0);
                atomicAdd(&csOut[gc+1], c1);
            }
        }
    }
}

__global__ __launch_bounds__(256) void sim_H1_sym() { sim_body<true >(b_H1, b_H1, g_r11, nullptr, g_d11); }
__global__ __launch_bounds__(256) void sim_H2_sym() { sim_body<true >(b_H2, b_H2, g_r22, nullptr, g_d22); }
__global__ __launch_bounds__(256) void sim_H_full() { sim_body<false>(b_H1, b_H2, g_r12, g_c12, g_d12); }

// ---------------- fp32 -> bf16 conversion ------------------------------------
__device__ __forceinline__ void conv_body(const float* __restrict__ src,
                                          bf16* __restrict__ dst, int n4)
{
    int idx = blockIdx.x * blockDim.x + threadIdx.x;
    if (idx < n4) {
        float4 v = ((const float4*)src)[idx];
        ((bf162*)dst)[idx*2+0] = __floats2bfloat162_rn(v.x, v.y);
        ((bf162*)dst)[idx*2+1] = __floats2bfloat162_rn(v.z, v.w);
    }
}
__global__ void conv_A1(const float* s) { conv_body(s, b_A1, NS*DD/4); }
__global__ void conv_A2(const float* s) { conv_body(s, b_A2, NS*DD/4); }
__global__ void conv_W1(const float* s) { conv_body(s, b_W1, DD*DD/4); }
__global__ void conv_W2(const float* s) { conv_body(s, b_W2, DD*DD/4); }
__global__ void conv_W3(const float* s) { conv_body(s, b_W3, DD*DD/4); }
__global__ void conv_W4(const float* s) { conv_body(s, b_W4, DD*DD/4); }

// ---------------- per-sample 32x32 transpose fp32 -> bf16 -------------------
__device__ __forceinline__ void trans_body(const float* __restrict__ in,
                                           bf16* __restrict__ out)
{
    __shared__ float t[32][33];
    const float* s = in  + (size_t)blockIdx.x * 1024;
    bf16*        d = out + (size_t)blockIdx.x * 1024;
    for (int i = threadIdx.x; i < 1024; i += 256) t[i >> 5][i & 31] = s[i];
    __syncthreads();
    for (int i = threadIdx.x; i < 1024; i += 256)
        d[i] = __float2bfloat16(t[i & 31][i >> 5]);
}
__global__ __launch_bounds__(256) void trans_A1(const float* in) { trans_body(in, b_A1); }
__global__ __launch_bounds__(256) void trans_A2(const float* in) { trans_body(in, b_A2); }

// ---------------- row L2 normalize bf16 in place, D = 1024 ------------------
__device__ __forceinline__ void norm_body(bf16* __restrict__ H)
{
    int row = blockIdx.x;
    uint2* p = (uint2*)(H + (size_t)row * DD) + threadIdx.x;  // 4 bf16 per thread
    uint2 raw = *p;
    bf162 v0 = *(bf162*)&raw.x;
    bf162 v1 = *(bf162*)&raw.y;
    float a = __bfloat162float(v0.x), b = __bfloat162float(v0.y);
    float c = __bfloat162float(v1.x), d = __bfloat162float(v1.y);
    float s = a*a + b*b + c*c + d*d;
    #pragma unroll
    for (int o = 16; o; o >>= 1) s += __shfl_xor_sync(0xffffffffu, s, o);
    __shared__ float red[8];
    int lane = threadIdx.x & 31, w = threadIdx.x >> 5;
    if (lane == 0) red[w] = s;
    __syncthreads();
    __shared__ float invn;
    if (threadIdx.x == 0) {
        float t = 0.f;
        #pragma unroll
        for (int i = 0; i < 8; i++) t += red[i];
        invn = rsqrtf(t);
    }
    __syncthreads();
    float iv = invn;
    uint2 outw;
    *(bf162*)&outw.x = __floats2bfloat162_rn(a*iv, b*iv);
    *(bf162*)&outw.y = __floats2bfloat162_rn(c*iv, d*iv);
    *p = outw;
}
__global__ __launch_bounds__(256) void norm_H1() { norm_body(b_H1); }
__global__ __launch_bounds__(256) void norm_H2() { norm_body(b_H2); }

// ---------------- stats zero / loss ------------------------------------------
__global__ void zero_stats(int zero_loss)
{
    int i = blockIdx.x * blockDim.x + threadIdx.x;
    if (i < NS) { g_r11[i] = 0.f; g_r22[i] = 0.f; g_r12[i] = 0.f; g_c12[i] = 0.f; }
    if (zero_loss && i < 2) g_loss[i] = 0.f;
}

__global__ void loss_reduce(int slot)
{
    int i = blockIdx.x * blockDim.x + threadIdx.x;
    float v = 0.f;
    if (i < NS) {
        float ld = logf(g_d12[i]);
        float l1 = logf(g_r11[i] + g_r12[i] - g_d11[i]) - ld;
        float l2 = logf(g_r22[i] + g_c12[i] - g_d22[i]) - ld;
        v = 0.5f * (l1 + l2) * (1.0f / NS);
    }
    #pragma unroll
    for (int o = 16; o; o >>= 1) v += __shfl_down_sync(0xffffffffu, v, o);
    if ((threadIdx.x & 31) == 0) atomicAdd(&g_loss[slot], v);
}

__global__ void finalize_k(const float* __restrict__ w_r1, float* __restrict__ out)
{
    float w = fminf(fmaxf(w_r1[0], 0.f), 1.f);
    out[0] = w * g_loss[0] + (1.f - w) * g_loss[1];
}

// ----------------------------------------------------------------------------
extern "C" void kernel_launch(void* const* d_in, const int* in_sizes, int n_in,
                              void* d_out, int out_size)
{
    const float* ta   = (const float*)d_in[0];
    const float* tb   = (const float*)d_in[1];
    const float* W1   = (const float*)d_in[2];
    const float* b1   = (const float*)d_in[3];
    const float* W2   = (const float*)d_in[4];
    const float* b2   = (const float*)d_in[5];
    const float* W3   = (const float*)d_in[6];
    const float* b3   = (const float*)d_in[7];
    const float* W4   = (const float*)d_in[8];
    const float* b4   = (const float*)d_in[9];
    const float* w_r1 = (const float*)d_in[10];
    float* out = (float*)d_out;

    dim3 gProj(DD / 128, NS / 128);      // 8 x 64
    dim3 gSim(NTILE, NTILE);             // 64 x 64 (sym self-prunes)
    int  zb  = (NS + 255) / 256;
    int  cbA = (NS*DD/4 + 255) / 256;
    int  cbW = (DD*DD/4 + 255) / 256;

    // ---- conversions ----
    conv_W1<<<cbW, 256>>>(W1);
    conv_W2<<<cbW, 256>>>(W2);
    conv_W3<<<cbW, 256>>>(W3);
    conv_W4<<<cbW, 256>>>(W4);
    zero_stats<<<zb, 256>>>(1);

    // ---- row view ----
    conv_A1<<<cbA, 256>>>(ta);
    conv_A2<<<cbA, 256>>>(tb);
    g_A1W1U1<<<gProj, 256>>>(b1);
    g_A2W1U2<<<gProj, 256>>>(b1);
    g_U1W2H1<<<gProj, 256>>>(b2);
    g_U2W2H2<<<gProj, 256>>>(b2);
    norm_H1<<<NS, 256>>>();
    norm_H2<<<NS, 256>>>();
    sim_H1_sym<<<gSim, 256>>>();
    sim_H2_sym<<<gSim, 256>>>();
    sim_H_full<<<gSim, 256>>>();
    loss_reduce<<<zb, 256>>>(0);

    // ---- column view ----
    trans_A1<<<NS, 256>>>(ta);
    trans_A2<<<NS, 256>>>(tb);
    zero_stats<<<zb, 256>>>(0);
    g_A1W3U1<<<gProj, 256>>>(b3);
    g_A2W3U2<<<gProj, 256>>>(b3);
    g_U1W4H1<<<gProj, 256>>>(b4);
    g_U2W4H2<<<gProj, 256>>>(b4);
    norm_H1<<<NS, 256>>>();
    norm_H2<<<NS, 256>>>();
    sim_H1_sym<<<gSim, 256>>>();
    sim_H2_sym<<<gSim, 256>>>();
    sim_H_full<<<gSim, 256>>>();
    loss_reduce<<<zb, 256>>>(1);

    finalize_k<<<1, 1>>>(w_r1, out);
}

// round 7
// speedup vs baseline: 1.2842x; 1.2842x over previous
#include <cuda_runtime.h>
#include <cuda_bf16.h>
#include <math.h>
#include <stdint.h>

// ----------------------------------------------------------------------------
// TContrastive: GRACE InfoNCE, bf16 mma.sync + cp.async 2-stage pipeline.
// (tcgen05 unavailable: harness compiles via compute_103 virtual arch.)
// ----------------------------------------------------------------------------

#define NS 8192
#define DD 1024
#define NTILE (NS / 128)
#define SMS 40                    // smem row stride in bf16 elems (80B)
#define STAGE_B 20480             // bytes per stage: A(10240) + B(10240)

typedef __nv_bfloat16 bf16;
typedef __nv_bfloat162 bf162;

__device__ bf16 b_A1[NS*DD];
__device__ bf16 b_A2[NS*DD];
__device__ bf16 b_U1[NS*DD];
__device__ bf16 b_U2[NS*DD];
__device__ bf16 b_H1[NS*DD];
__device__ bf16 b_H2[NS*DD];
__device__ bf16 b_W1[DD*DD];
__device__ bf16 b_W2[DD*DD];
__device__ bf16 b_W3[DD*DD];
__device__ bf16 b_W4[DD*DD];
__device__ float g_r11[NS], g_r22[NS], g_r12[NS], g_c12[NS];
__device__ float g_d11[NS], g_d22[NS], g_d12[NS];
__device__ float g_loss[2];

// ---------------- primitive wrappers ----------------------------------------
__device__ __forceinline__ void ldm_x4(uint32_t& r0, uint32_t& r1, uint32_t& r2,
                                       uint32_t& r3, const bf16* p)
{
    uint32_t a = (uint32_t)__cvta_generic_to_shared(p);
    asm volatile("ldmatrix.sync.aligned.m8n8.x4.shared.b16 {%0,%1,%2,%3}, [%4];"
                 : "=r"(r0), "=r"(r1), "=r"(r2), "=r"(r3) : "r"(a));
}

__device__ __forceinline__ void mma16816(float* c, const uint32_t* a, const uint32_t* b)
{
    asm volatile("mma.sync.aligned.m16n8k16.row.col.f32.bf16.bf16.f32 "
                 "{%0,%1,%2,%3}, {%4,%5,%6,%7}, {%8,%9}, {%0,%1,%2,%3};"
                 : "+f"(c[0]), "+f"(c[1]), "+f"(c[2]), "+f"(c[3])
                 : "r"(a[0]), "r"(a[1]), "r"(a[2]), "r"(a[3]),
                   "r"(b[0]), "r"(b[1]));
}

__device__ __forceinline__ void cpa16(uint32_t dst, const void* src)
{ asm volatile("cp.async.cg.shared.global [%0], [%1], 16;" :: "r"(dst), "l"(src)); }

#define CP_COMMIT() asm volatile("cp.async.commit_group;" ::: "memory")
#define CP_WAIT1()  asm volatile("cp.async.wait_group 1;" ::: "memory")
#define CP_WAIT0()  asm volatile("cp.async.wait_group 0;" ::: "memory")

// ---------------- pipelined mainloop -----------------------------------------
// 128x128 fp32 tile of A(m0..)·B(n0..)^T, K=1024. Warp grid 2x4: warp (wm,wn)
// owns rows wm*64.., cols wn*32... C frag: c0,c1 row grp cols qid*2; c2,c3 row grp+8.
// K-chunk 32 elems, 2 smem stages, cp.async prefetch of chunk c+1 during c.
__device__ __forceinline__ void mma_mainloop(const bf16* __restrict__ A,
    const bf16* __restrict__ B, int m0, int n0, char* sm, float acc[4][4][4])
{
    const int tid = threadIdx.x;
    const int lane = tid & 31;
    const int wid = tid >> 5;
    const int wm = wid >> 2, wn = wid & 3;
    const int r = lane & 7, tsel = lane >> 3;
    const int a_row = ((tsel & 1) << 3) + r;
    const int a_col = (tsel >> 1) << 3;
    const int b_row = ((tsel >> 1) << 3) + r;
    const int b_col = (tsel & 1) << 3;

    // per-thread 4 copy slots: ids 0..1023 -> half(A/B), row, 16B-quarter
    const char* src[4];
    uint32_t dof[4];
    const uint32_t smb = (uint32_t)__cvta_generic_to_shared(sm);
    #pragma unroll
    for (int it = 0; it < 4; it++) {
        int id = it * 256 + tid;
        int half = id >> 9, rem = id & 511;
        int row = rem >> 2, q = rem & 3;
        src[it] = (const char*)((half ? B + (size_t)(n0 + row) * DD
                                      : A + (size_t)(m0 + row) * DD) + q * 8);
        dof[it] = smb + half * 10240u + (uint32_t)(row * 80 + q * 16);
    }

    #pragma unroll
    for (int i = 0; i < 4; i++)
        #pragma unroll
        for (int j = 0; j < 4; j++)
            #pragma unroll
            for (int q = 0; q < 4; q++) acc[i][j][q] = 0.f;

    // prefetch chunk 0 -> stage 0
    #pragma unroll
    for (int it = 0; it < 4; it++) cpa16(dof[it], src[it]);
    CP_COMMIT();

    for (int c = 0; c < 32; c++) {
        int s = c & 1;
        if (c + 1 < 32) {   // prefetch next chunk into other stage
            uint32_t od = (uint32_t)((c + 1) & 1) * STAGE_B;
            const size_t og = (size_t)(c + 1) * 64;   // 32 elems = 64B
            #pragma unroll
            for (int it = 0; it < 4; it++) cpa16(dof[it] + od, src[it] + og);
            CP_COMMIT();
            CP_WAIT1();
        } else {
            CP_WAIT0();
        }
        __syncthreads();

        const bf16* sA = (const bf16*)(sm + s * STAGE_B);
        const bf16* sB = (const bf16*)(sm + s * STAGE_B + 10240);
        #pragma unroll
        for (int ks = 0; ks < 32; ks += 16) {
            uint32_t a[4][4], b[4][2];
            #pragma unroll
            for (int ti = 0; ti < 4; ti++)
                ldm_x4(a[ti][0], a[ti][1], a[ti][2], a[ti][3],
                       &sA[(wm*64 + ti*16 + a_row)*SMS + ks + a_col]);
            #pragma unroll
            for (int pp = 0; pp < 2; pp++)
                ldm_x4(b[2*pp][0], b[2*pp][1], b[2*pp+1][0], b[2*pp+1][1],
                       &sB[(wn*32 + pp*16 + b_row)*SMS + ks + b_col]);
            #pragma unroll
            for (int ti = 0; ti < 4; ti++)
                #pragma unroll
                for (int tj = 0; tj < 4; tj++)
                    mma16816(acc[ti][tj], a[ti], b[tj]);
        }
        __syncthreads();
    }
}

// ---------------- projection GEMM: C = [elu](A·W^T + bias), bf16 out --------
template<int MODE>
__device__ __forceinline__ void gemm_body(const bf16* __restrict__ A,
    const bf16* __restrict__ W, const float* __restrict__ bias,
    bf16* __restrict__ C)
{
    __shared__ __align__(16) char sm[2 * STAGE_B];
    const int m0 = blockIdx.y * 128, n0 = blockIdx.x * 128;
    const int lane = threadIdx.x & 31, wid = threadIdx.x >> 5;
    const int wm = wid >> 2, wn = wid & 3;
    const int grp = lane >> 2, qid = lane & 3;

    float acc[4][4][4];
    mma_mainloop(A, W, m0, n0, sm, acc);

    #pragma unroll
    for (int tj = 0; tj < 4; tj++) {
        int gc = n0 + wn*32 + tj*8 + qid*2;
        float bv0 = bias[gc], bv1 = bias[gc+1];
        #pragma unroll
        for (int ti = 0; ti < 4; ti++)
            #pragma unroll
            for (int h = 0; h < 2; h++) {
                int gr = m0 + wm*64 + ti*16 + h*8 + grp;
                float v0 = acc[ti][tj][h*2+0] + bv0;
                float v1 = acc[ti][tj][h*2+1] + bv1;
                if (MODE == 1) {
                    v0 = v0 > 0.f ? v0 : expm1f(v0);
                    v1 = v1 > 0.f ? v1 : expm1f(v1);
                }
                *(bf162*)(C + (size_t)gr * DD + gc) = __floats2bfloat162_rn(v0, v1);
            }
    }
}

__global__ __launch_bounds__(256) void g_A1W1U1(const float* b) { gemm_body<1>(b_A1, b_W1, b, b_U1); }
__global__ __launch_bounds__(256) void g_A2W1U2(const float* b) { gemm_body<1>(b_A2, b_W1, b, b_U2); }
__global__ __launch_bounds__(256) void g_U1W2H1(const float* b) { gemm_body<0>(b_U1, b_W2, b, b_H1); }
__global__ __launch_bounds__(256) void g_U2W2H2(const float* b) { gemm_body<0>(b_U2, b_W2, b, b_H2); }
__global__ __launch_bounds__(256) void g_A1W3U1(const float* b) { gemm_body<1>(b_A1, b_W3, b, b_U1); }
__global__ __launch_bounds__(256) void g_A2W3U2(const float* b) { gemm_body<1>(b_A2, b_W3, b, b_U2); }
__global__ __launch_bounds__(256) void g_U1W4H1(const float* b) { gemm_body<0>(b_U1, b_W4, b, b_H1); }
__global__ __launch_bounds__(256) void g_U2W4H2(const float* b) { gemm_body<0>(b_U2, b_W4, b, b_H2); }

// ---------------- fused exp-similarity + reductions -------------------------
template<bool SYM>
__device__ __forceinline__ void sim_body(const bf16* __restrict__ A,
    const bf16* __restrict__ B, float* __restrict__ rs, float* __restrict__ cs,
    float* __restrict__ dg)
{
    const int bi = blockIdx.y;
    const int bj = SYM ? (bi + blockIdx.x) : blockIdx.x;
    if (SYM && bj >= NTILE) return;

    __shared__ __align__(16) char sm[2 * STAGE_B];
    const int m0 = bi * 128, n0 = bj * 128;
    const int lane = threadIdx.x & 31, wid = threadIdx.x >> 5;
    const int wm = wid >> 2, wn = wid & 3;
    const int grp = lane >> 2, qid = lane & 3;
    const bool diag = (bi == bj);

    float acc[4][4][4];
    mma_mainloop(A, B, m0, n0, sm, acc);

    #pragma unroll
    for (int ti = 0; ti < 4; ti++)
        #pragma unroll
        for (int h = 0; h < 2; h++) {
            int gr = m0 + wm*64 + ti*16 + h*8 + grp;
            float rsum = 0.f;
            #pragma unroll
            for (int tj = 0; tj < 4; tj++) {
                int gc = n0 + wn*32 + tj*8 + qid*2;
                float e0 = __expf(2.f * acc[ti][tj][h*2+0]);
                float e1 = __expf(2.f * acc[ti][tj][h*2+1]);
                acc[ti][tj][h*2+0] = e0;
                acc[ti][tj][h*2+1] = e1;
                rsum += e0 + e1;
                if (diag) {
                    if (gr == gc)     dg[gr] = e0;
                    if (gr == gc + 1) dg[gr] = e1;
                }
            }
            rsum += __shfl_down_sync(0xffffffffu, rsum, 2, 4);
            rsum += __shfl_down_sync(0xffffffffu, rsum, 1, 4);
            if (qid == 0) atomicAdd(&rs[gr], rsum);
        }

    const bool doCols = (!SYM) || (bj > bi);
    if (doCols) {
        float* csOut = SYM ? rs : cs;
        #pragma unroll
        for (int tj = 0; tj < 4; tj++) {
            float c0 = 0.f, c1 = 0.f;
            #pragma unroll
            for (int ti = 0; ti < 4; ti++) {
                c0 += acc[ti][tj][0] + acc[ti][tj][2];
                c1 += acc[ti][tj][1] + acc[ti][tj][3];
            }
            #pragma unroll
            for (int o = 4; o <= 16; o <<= 1) {
                c0 += __shfl_xor_sync(0xffffffffu, c0, o);
                c1 += __shfl_xor_sync(0xffffffffu, c1, o);
            }
            if (grp == 0) {
                int gc = n0 + wn*32 + tj*8 + qid*2;
                atomicAdd(&csOut[gc],   c0);
                atomicAdd(&csOut[gc+1], c1);
            }
        }
    }
}

__global__ __launch_bounds__(256) void sim_H1_sym() { sim_body<true >(b_H1, b_H1, g_r11, nullptr, g_d11); }
__global__ __launch_bounds__(256) void sim_H2_sym() { sim_body<true >(b_H2, b_H2, g_r22, nullptr, g_d22); }
__global__ __launch_bounds__(256) void sim_H_full() { sim_body<false>(b_H1, b_H2, g_r12, g_c12, g_d12); }

// ---------------- aux kernels ------------------------------------------------
__device__ __forceinline__ void conv_body(const float* __restrict__ s,
                                          bf16* __restrict__ d, int n4)
{
    int i = blockIdx.x * blockDim.x + threadIdx.x;
    if (i < n4) {
        float4 v = ((const float4*)s)[i];
        ((bf162*)d)[i*2+0] = __floats2bfloat162_rn(v.x, v.y);
        ((bf162*)d)[i*2+1] = __floats2bfloat162_rn(v.z, v.w);
    }
}
__global__ void conv_A1(const float* s) { conv_body(s, b_A1, NS*DD/4); }
__global__ void conv_A2(const float* s) { conv_body(s, b_A2, NS*DD/4); }
__global__ void conv_W1(const float* s) { conv_body(s, b_W1, DD*DD/4); }
__global__ void conv_W2(const float* s) { conv_body(s, b_W2, DD*DD/4); }
__global__ void conv_W3(const float* s) { conv_body(s, b_W3, DD*DD/4); }
__global__ void conv_W4(const float* s) { conv_body(s, b_W4, DD*DD/4); }

__device__ __forceinline__ void trans_body(const float* __restrict__ in,
                                           bf16* __restrict__ out)
{
    __shared__ float t[32][33];
    const float* s = in  + (size_t)blockIdx.x * 1024;
    bf16*        d = out + (size_t)blockIdx.x * 1024;
    for (int i = threadIdx.x; i < 1024; i += 256) t[i >> 5][i & 31] = s[i];
    __syncthreads();
    for (int i = threadIdx.x; i < 1024; i += 256)
        d[i] = __float2bfloat16(t[i & 31][i >> 5]);
}
__global__ __launch_bounds__(256) void trans_A1(const float* in) { trans_body(in, b_A1); }
__global__ __launch_bounds__(256) void trans_A2(const float* in) { trans_body(in, b_A2); }

__device__ __forceinline__ void norm_body(bf16* __restrict__ H)
{
    int row = blockIdx.x;
    uint2* p = (uint2*)(H + (size_t)row * DD) + threadIdx.x;
    uint2 raw = *p;
    bf162 v0 = *(bf162*)&raw.x;
    bf162 v1 = *(bf162*)&raw.y;
    float a = __bfloat162float(v0.x), b = __bfloat162float(v0.y);
    float c = __bfloat162float(v1.x), d = __bfloat162float(v1.y);
    float s = a*a + b*b + c*c + d*d;
    #pragma unroll
    for (int o = 16; o; o >>= 1) s += __shfl_xor_sync(0xffffffffu, s, o);
    __shared__ float red[8];
    int lane = threadIdx.x & 31, w = threadIdx.x >> 5;
    if (lane == 0) red[w] = s;
    __syncthreads();
    __shared__ float invn;
    if (threadIdx.x == 0) {
        float t = 0.f;
        #pragma unroll
        for (int i = 0; i < 8; i++) t += red[i];
        invn = rsqrtf(t);
    }
    __syncthreads();
    float iv = invn;
    uint2 ow;
    *(bf162*)&ow.x = __floats2bfloat162_rn(a*iv, b*iv);
    *(bf162*)&ow.y = __floats2bfloat162_rn(c*iv, d*iv);
    *p = ow;
}
__global__ __launch_bounds__(256) void norm_H1() { norm_body(b_H1); }
__global__ __launch_bounds__(256) void norm_H2() { norm_body(b_H2); }

__global__ void zero_stats(int zl)
{
    int i = blockIdx.x * blockDim.x + threadIdx.x;
    if (i < NS) { g_r11[i] = 0.f; g_r22[i] = 0.f; g_r12[i] = 0.f; g_c12[i] = 0.f; }
    if (zl && i < 2) g_loss[i] = 0.f;
}

__global__ void loss_reduce(int slot)
{
    int i = blockIdx.x * blockDim.x + threadIdx.x;
    float v = 0.f;
    if (i < NS) {
        float ld = logf(g_d12[i]);
        float l1 = logf(g_r11[i] + g_r12[i] - g_d11[i]) - ld;
        float l2 = logf(g_r22[i] + g_c12[i] - g_d22[i]) - ld;
        v = 0.5f * (l1 + l2) * (1.0f / NS);
    }
    #pragma unroll
    for (int o = 16; o; o >>= 1) v += __shfl_down_sync(0xffffffffu, v, o);
    if ((threadIdx.x & 31) == 0) atomicAdd(&g_loss[slot], v);
}

__global__ void finalize_k(const float* __restrict__ w_r1, float* __restrict__ out)
{
    float w = fminf(fmaxf(w_r1[0], 0.f), 1.f);
    out[0] = w * g_loss[0] + (1.f - w) * g_loss[1];
}

// ----------------------------------------------------------------------------
extern "C" void kernel_launch(void* const* d_in, const int* in_sizes, int n_in,
                              void* d_out, int out_size)
{
    const float* ta   = (const float*)d_in[0];
    const float* tb   = (const float*)d_in[1];
    const float* W1   = (const float*)d_in[2];
    const float* b1   = (const float*)d_in[3];
    const float* W2   = (const float*)d_in[4];
    const float* b2   = (const float*)d_in[5];
    const float* W3   = (const float*)d_in[6];
    const float* b3   = (const float*)d_in[7];
    const float* W4   = (const float*)d_in[8];
    const float* b4   = (const float*)d_in[9];
    const float* w_r1 = (const float*)d_in[10];
    float* out = (float*)d_out;

    dim3 gProj(DD / 128, NS / 128);
    dim3 gSim(NTILE, NTILE);
    int  zb  = (NS + 255) / 256;
    int  cbA = (NS*DD/4 + 255) / 256;
    int  cbW = (DD*DD/4 + 255) / 256;

    conv_W1<<<cbW, 256>>>(W1);
    conv_W2<<<cbW, 256>>>(W2);
    conv_W3<<<cbW, 256>>>(W3);
    conv_W4<<<cbW, 256>>>(W4);
    zero_stats<<<zb, 256>>>(1);

    conv_A1<<<cbA, 256>>>(ta);
    conv_A2<<<cbA, 256>>>(tb);
    g_A1W1U1<<<gProj, 256>>>(b1);
    g_A2W1U2<<<gProj, 256>>>(b1);
    g_U1W2H1<<<gProj, 256>>>(b2);
    g_U2W2H2<<<gProj, 256>>>(b2);
    norm_H1<<<NS, 256>>>();
    norm_H2<<<NS, 256>>>();
    sim_H1_sym<<<gSim, 256>>>();
    sim_H2_sym<<<gSim, 256>>>();
    sim_H_full<<<gSim, 256>>>();
    loss_reduce<<<zb, 256>>>(0);

    trans_A1<<<NS, 256>>>(ta);
    trans_A2<<<NS, 256>>>(tb);
    zero_stats<<<zb, 256>>>(0);
    g_A1W3U1<<<gProj, 256>>>(b3);
    g_A2W3U2<<<gProj, 256>>>(b3);
    g_U1W4H1<<<gProj, 256>>>(b4);
    g_U2W4H2<<<gProj, 256>>>(b4);
    norm_H1<<<NS, 256>>>();
    norm_H2<<<NS, 256>>>();
    sim_H1_sym<<<gSim, 256>>>();
    sim_H2_sym<<<gSim, 256>>>();
    sim_H_full<<<gSim, 256>>>();
    loss_reduce<<<zb, 256>>>(1);

    finalize_k<<<1, 1>>>(w_r1, out);
}

// round 8
// speedup vs baseline: 1.2987x; 1.0112x over previous
#include <cuda_runtime.h>
#include <cuda_bf16.h>
#include <math.h>
#include <stdint.h>

// ----------------------------------------------------------------------------
// TContrastive: GRACE InfoNCE, bf16 mma.sync, 128x256 CTA tile, cp.async
// 2-stage pipeline, 64B-row XOR-swizzled smem (48KB exactly).
// ----------------------------------------------------------------------------

#define NS 8192
#define DD 1024
#define NTILE 64                  // 128-row tiles
#define STAGE_B 24576             // A 8192B + B 16384B
#define RSB 2048                  // global row stride bytes (DD*2)

typedef __nv_bfloat16 bf16;
typedef __nv_bfloat162 bf162;

__device__ bf16 b_A1[NS*DD];
__device__ bf16 b_A2[NS*DD];
__device__ bf16 b_U1[NS*DD];
__device__ bf16 b_U2[NS*DD];
__device__ bf16 b_H1[NS*DD];
__device__ bf16 b_H2[NS*DD];
__device__ bf16 b_W1[DD*DD];
__device__ bf16 b_W2[DD*DD];
__device__ bf16 b_W3[DD*DD];
__device__ bf16 b_W4[DD*DD];
__device__ float g_r11[NS], g_r22[NS], g_r12[NS], g_c12[NS];
__device__ float g_d11[NS], g_d22[NS], g_d12[NS];
__device__ float g_loss[2];

// ---------------- primitives -------------------------------------------------
__device__ __forceinline__ void ldm_x4(uint32_t& r0, uint32_t& r1, uint32_t& r2,
                                       uint32_t& r3, uint32_t a)
{
    asm volatile("ldmatrix.sync.aligned.m8n8.x4.shared.b16 {%0,%1,%2,%3}, [%4];"
                 : "=r"(r0), "=r"(r1), "=r"(r2), "=r"(r3) : "r"(a));
}
__device__ __forceinline__ void mma16816(float* c, const uint32_t* a, const uint32_t* b)
{
    asm volatile("mma.sync.aligned.m16n8k16.row.col.f32.bf16.bf16.f32 "
                 "{%0,%1,%2,%3}, {%4,%5,%6,%7}, {%8,%9}, {%0,%1,%2,%3};"
                 : "+f"(c[0]), "+f"(c[1]), "+f"(c[2]), "+f"(c[3])
                 : "r"(a[0]), "r"(a[1]), "r"(a[2]), "r"(a[3]),
                   "r"(b[0]), "r"(b[1]));
}
__device__ __forceinline__ void cpa16(uint32_t dst, const void* src)
{ asm volatile("cp.async.cg.shared.global [%0], [%1], 16;" :: "r"(dst), "l"(src)); }
#define CP_COMMIT() asm volatile("cp.async.commit_group;" ::: "memory")
#define CP_WAIT1()  asm volatile("cp.async.wait_group 1;" ::: "memory")
#define CP_WAIT0()  asm volatile("cp.async.wait_group 0;" ::: "memory")

// smem byte offset for (row, 16B-chunk q): 64B rows, XOR swizzle
__device__ __forceinline__ uint32_t swz(int row, int q)
{ return (uint32_t)(row * 64 + ((q ^ ((row >> 1) & 3)) << 4)); }

// ---------------- mainloop: 128x256 fp32 tile of A·B^T, K=1024 --------------
// Warp grid 2x4 (wm, wn); warp tile 64x64; acc[ti 0..3][tj 0..7][4].
// C frag map: c0,c1 -> row grp, cols qid*2,+1; c2,c3 -> row grp+8.
__device__ __forceinline__ void mma_mainloop(const bf16* __restrict__ A,
    const bf16* __restrict__ B, int m0, int n0, char* sm, float acc[4][8][4])
{
    const int tid = threadIdx.x;
    const int lane = tid & 31, wid = tid >> 5;
    const int wm = wid >> 2, wn = wid & 3;
    const int r = lane & 7, tsel = lane >> 3;
    const int a_row = ((tsel & 1) << 3) + r;
    const int a_col = (tsel >> 1) << 3;
    const int b_row = ((tsel >> 1) << 3) + r;
    const int b_col = (tsel & 1) << 3;

    // copy setup: thread covers A rows r0, r0+64; B rows r0+{0,64,128,192}
    const int r0 = tid >> 2, q = tid & 3;
    const char* pA = (const char*)(A + (size_t)(m0 + r0) * DD) + q * 16;
    const char* pB = (const char*)(B + (size_t)(n0 + r0) * DD) + q * 16;
    const uint32_t smb = (uint32_t)__cvta_generic_to_shared(sm);
    const uint32_t dA = smb + swz(r0, q);
    const uint32_t dB = smb + 8192u + swz(r0, q);   // swizzle bits invariant to +64k rows

    #pragma unroll
    for (int i = 0; i < 4; i++)
        #pragma unroll
        for (int j = 0; j < 8; j++)
            #pragma unroll
            for (int p = 0; p < 4; p++) acc[i][j][p] = 0.f;

    cpa16(dA, pA);              cpa16(dA + 4096, pA + 64*RSB);
    cpa16(dB, pB);              cpa16(dB + 4096, pB + 64*RSB);
    cpa16(dB + 8192, pB + 128*RSB); cpa16(dB + 12288, pB + 192*RSB);
    CP_COMMIT();

    for (int c = 0; c < 32; c++) {
        if (c + 1 < 32) {
            uint32_t od = (uint32_t)((c + 1) & 1) * STAGE_B;
            const size_t og = (size_t)(c + 1) * 64;
            cpa16(dA + od, pA + og);               cpa16(dA + od + 4096, pA + og + 64*RSB);
            cpa16(dB + od, pB + og);               cpa16(dB + od + 4096, pB + og + 64*RSB);
            cpa16(dB + od + 8192, pB + og + 128*RSB); cpa16(dB + od + 12288, pB + og + 192*RSB);
            CP_COMMIT();
            CP_WAIT1();
        } else {
            CP_WAIT0();
        }
        __syncthreads();

        const uint32_t sA = smb + (uint32_t)(c & 1) * STAGE_B;
        const uint32_t sB = sA + 8192u;
        #pragma unroll
        for (int ks = 0; ks < 32; ks += 16) {
            uint32_t a[4][4], b[8][2];
            #pragma unroll
            for (int ti = 0; ti < 4; ti++) {
                int rr = wm*64 + ti*16 + a_row;
                ldm_x4(a[ti][0], a[ti][1], a[ti][2], a[ti][3],
                       sA + swz(rr, (ks + a_col) >> 3));
            }
            #pragma unroll
            for (int pp = 0; pp < 4; pp++) {
                int rr = wn*64 + pp*16 + b_row;
                ldm_x4(b[2*pp][0], b[2*pp][1], b[2*pp+1][0], b[2*pp+1][1],
                       sB + swz(rr, (ks + b_col) >> 3));
            }
            #pragma unroll
            for (int ti = 0; ti < 4; ti++)
                #pragma unroll
                for (int tj = 0; tj < 8; tj++)
                    mma16816(acc[ti][tj], a[ti], b[tj]);
        }
        __syncthreads();
    }
}

// ---------------- projection GEMM: C = [elu](A·W^T + bias), bf16 out --------
template<int MODE>
__device__ __forceinline__ void gemm_body(const bf16* __restrict__ A,
    const bf16* __restrict__ W, const float* __restrict__ bias,
    bf16* __restrict__ C)
{
    __shared__ __align__(16) char sm[2 * STAGE_B];
    const int m0 = blockIdx.y * 128, n0 = blockIdx.x * 256;
    const int lane = threadIdx.x & 31, wid = threadIdx.x >> 5;
    const int wm = wid >> 2, wn = wid & 3;
    const int grp = lane >> 2, qid = lane & 3;

    float acc[4][8][4];
    mma_mainloop(A, W, m0, n0, sm, acc);

    #pragma unroll
    for (int tj = 0; tj < 8; tj++) {
        int gc = n0 + wn*64 + tj*8 + qid*2;
        float bv0 = bias[gc], bv1 = bias[gc+1];
        #pragma unroll
        for (int ti = 0; ti < 4; ti++)
            #pragma unroll
            for (int h = 0; h < 2; h++) {
                int gr = m0 + wm*64 + ti*16 + h*8 + grp;
                float v0 = acc[ti][tj][h*2+0] + bv0;
                float v1 = acc[ti][tj][h*2+1] + bv1;
                if (MODE == 1) {
                    v0 = v0 > 0.f ? v0 : expm1f(v0);
                    v1 = v1 > 0.f ? v1 : expm1f(v1);
                }
                *(bf162*)(C + (size_t)gr * DD + gc) = __floats2bfloat162_rn(v0, v1);
            }
    }
}

__global__ __launch_bounds__(256) void g_A1W1U1(const float* b) { gemm_body<1>(b_A1, b_W1, b, b_U1); }
__global__ __launch_bounds__(256) void g_A2W1U2(const float* b) { gemm_body<1>(b_A2, b_W1, b, b_U2); }
__global__ __launch_bounds__(256) void g_U1W2H1(const float* b) { gemm_body<0>(b_U1, b_W2, b, b_H1); }
__global__ __launch_bounds__(256) void g_U2W2H2(const float* b) { gemm_body<0>(b_U2, b_W2, b, b_H2); }
__global__ __launch_bounds__(256) void g_A1W3U1(const float* b) { gemm_body<1>(b_A1, b_W3, b, b_U1); }
__global__ __launch_bounds__(256) void g_A2W3U2(const float* b) { gemm_body<1>(b_A2, b_W3, b, b_U2); }
__global__ __launch_bounds__(256) void g_U1W4H1(const float* b) { gemm_body<0>(b_U1, b_W4, b, b_H1); }
__global__ __launch_bounds__(256) void g_U2W4H2(const float* b) { gemm_body<0>(b_U2, b_W4, b, b_H2); }

// ---------------- fused exp-similarity + reductions -------------------------
// Tile = 128 rows x 256 cols. Each warp's 64 cols lie in ONE 128-col half:
// chalf = 2*bj2 + (wn>>1). SYM: bj2 = bi/2 + blockIdx.x (exit if >=32);
// warp participates iff chalf >= bi; col sums folded into rs iff chalf > bi;
// diag extracted iff chalf == bi. FULL: bj2 = blockIdx.x, all valid, cols->cs.
template<bool SYM>
__device__ __forceinline__ void sim_body(const bf16* __restrict__ A,
    const bf16* __restrict__ B, float* __restrict__ rs, float* __restrict__ cs,
    float* __restrict__ dg)
{
    const int bi = blockIdx.y;
    const int bj2 = SYM ? (bi / 2 + blockIdx.x) : blockIdx.x;
    if (SYM && bj2 >= 32) return;

    __shared__ __align__(16) char sm[2 * STAGE_B];
    const int m0 = bi * 128, n0 = bj2 * 256;
    const int lane = threadIdx.x & 31, wid = threadIdx.x >> 5;
    const int wm = wid >> 2, wn = wid & 3;
    const int grp = lane >> 2, qid = lane & 3;

    float acc[4][8][4];
    mma_mainloop(A, B, m0, n0, sm, acc);

    const int chalf = 2*bj2 + (wn >> 1);
    if (SYM && chalf < bi) return;          // warp-uniform; no further barriers
    const bool diag = (chalf == bi);
    const bool doCols = (!SYM) || (chalf > bi);
    float* csOut = SYM ? rs : cs;

    #pragma unroll
    for (int ti = 0; ti < 4; ti++)
        #pragma unroll
        for (int h = 0; h < 2; h++) {
            int gr = m0 + wm*64 + ti*16 + h*8 + grp;
            float rsum = 0.f;
            #pragma unroll
            for (int tj = 0; tj < 8; tj++) {
                int gc = n0 + wn*64 + tj*8 + qid*2;
                float e0 = __expf(2.f * acc[ti][tj][h*2+0]);
                float e1 = __expf(2.f * acc[ti][tj][h*2+1]);
                acc[ti][tj][h*2+0] = e0;
                acc[ti][tj][h*2+1] = e1;
                rsum += e0 + e1;
                if (diag) {
                    if (gr == gc)     dg[gr] = e0;
                    if (gr == gc + 1) dg[gr] = e1;
                }
            }
            rsum += __shfl_down_sync(0xffffffffu, rsum, 2, 4);
            rsum += __shfl_down_sync(0xffffffffu, rsum, 1, 4);
            if (qid == 0) atomicAdd(&rs[gr], rsum);
        }

    if (doCols) {
        #pragma unroll
        for (int tj = 0; tj < 8; tj++) {
            float c0 = 0.f, c1 = 0.f;
            #pragma unroll
            for (int ti = 0; ti < 4; ti++) {
                c0 += acc[ti][tj][0] + acc[ti][tj][2];
                c1 += acc[ti][tj][1] + acc[ti][tj][3];
            }
            #pragma unroll
            for (int o = 4; o <= 16; o <<= 1) {
                c0 += __shfl_xor_sync(0xffffffffu, c0, o);
                c1 += __shfl_xor_sync(0xffffffffu, c1, o);
            }
            if (grp == 0) {
                int gc = n0 + wn*64 + tj*8 + qid*2;
                atomicAdd(&csOut[gc],   c0);
                atomicAdd(&csOut[gc+1], c1);
            }
        }
    }
}

__global__ __launch_bounds__(256) void sim_H1_sym() { sim_body<true >(b_H1, b_H1, g_r11, nullptr, g_d11); }
__global__ __launch_bounds__(256) void sim_H2_sym() { sim_body<true >(b_H2, b_H2, g_r22, nullptr, g_d22); }
__global__ __launch_bounds__(256) void sim_H_full() { sim_body<false>(b_H1, b_H2, g_r12, g_c12, g_d12); }

// ---------------- aux kernels ------------------------------------------------
__device__ __forceinline__ void conv_body(const float* __restrict__ s,
                                          bf16* __restrict__ d, int n4)
{
    int i = blockIdx.x * blockDim.x + threadIdx.x;
    if (i < n4) {
        float4 v = ((const float4*)s)[i];
        ((bf162*)d)[i*2+0] = __floats2bfloat162_rn(v.x, v.y);
        ((bf162*)d)[i*2+1] = __floats2bfloat162_rn(v.z, v.w);
    }
}
__global__ void conv_A1(const float* s) { conv_body(s, b_A1, NS*DD/4); }
__global__ void conv_A2(const float* s) { conv_body(s, b_A2, NS*DD/4); }
__global__ void conv_W1(const float* s) { conv_body(s, b_W1, DD*DD/4); }
__global__ void conv_W2(const float* s) { conv_body(s, b_W2, DD*DD/4); }
__global__ void conv_W3(const float* s) { conv_body(s, b_W3, DD*DD/4); }
__global__ void conv_W4(const float* s) { conv_body(s, b_W4, DD*DD/4); }

__device__ __forceinline__ void trans_body(const float* __restrict__ in,
                                           bf16* __restrict__ out)
{
    __shared__ float t[32][33];
    const float* s = in  + (size_t)blockIdx.x * 1024;
    bf16*        d = out + (size_t)blockIdx.x * 1024;
    for (int i = threadIdx.x; i < 1024; i += 256) t[i >> 5][i & 31] = s[i];
    __syncthreads();
    for (int i = threadIdx.x; i < 1024; i += 256)
        d[i] = __float2bfloat16(t[i & 31][i >> 5]);
}
__global__ __launch_bounds__(256) void trans_A1(const float* in) { trans_body(in, b_A1); }
__global__ __launch_bounds__(256) void trans_A2(const float* in) { trans_body(in, b_A2); }

__device__ __forceinline__ void norm_body(bf16* __restrict__ H)
{
    int row = blockIdx.x;
    uint2* p = (uint2*)(H + (size_t)row * DD) + threadIdx.x;
    uint2 raw = *p;
    bf162 v0 = *(bf162*)&raw.x;
    bf162 v1 = *(bf162*)&raw.y;
    float a = __bfloat162float(v0.x), b = __bfloat162float(v0.y);
    float c = __bfloat162float(v1.x), d = __bfloat162float(v1.y);
    float s = a*a + b*b + c*c + d*d;
    #pragma unroll
    for (int o = 16; o; o >>= 1) s += __shfl_xor_sync(0xffffffffu, s, o);
    __shared__ float red[8];
    int lane = threadIdx.x & 31, w = threadIdx.x >> 5;
    if (lane == 0) red[w] = s;
    __syncthreads();
    __shared__ float invn;
    if (threadIdx.x == 0) {
        float t = 0.f;
        #pragma unroll
        for (int i = 0; i < 8; i++) t += red[i];
        invn = rsqrtf(t);
    }
    __syncthreads();
    float iv = invn;
    uint2 ow;
    *(bf162*)&ow.x = __floats2bfloat162_rn(a*iv, b*iv);
    *(bf162*)&ow.y = __floats2bfloat162_rn(c*iv, d*iv);
    *p = ow;
}
__global__ __launch_bounds__(256) void norm_H1() { norm_body(b_H1); }
__global__ __launch_bounds__(256) void norm_H2() { norm_body(b_H2); }

__global__ void zero_stats(int zl)
{
    int i = blockIdx.x * blockDim.x + threadIdx.x;
    if (i < NS) { g_r11[i] = 0.f; g_r22[i] = 0.f; g_r12[i] = 0.f; g_c12[i] = 0.f; }
    if (zl && i < 2) g_loss[i] = 0.f;
}

__global__ void loss_reduce(int slot)
{
    int i = blockIdx.x * blockDim.x + threadIdx.x;
    float v = 0.f;
    if (i < NS) {
        float ld = logf(g_d12[i]);
        float l1 = logf(g_r11[i] + g_r12[i] - g_d11[i]) - ld;
        float l2 = logf(g_r22[i] + g_c12[i] - g_d22[i]) - ld;
        v = 0.5f * (l1 + l2) * (1.0f / NS);
    }
    #pragma unroll
    for (int o = 16; o; o >>= 1) v += __shfl_down_sync(0xffffffffu, v, o);
    if ((threadIdx.x & 31) == 0) atomicAdd(&g_loss[slot], v);
}

__global__ void finalize_k(const float* __restrict__ w_r1, float* __restrict__ out)
{
    float w = fminf(fmaxf(w_r1[0], 0.f), 1.f);
    out[0] = w * g_loss[0] + (1.f - w) * g_loss[1];
}

// ----------------------------------------------------------------------------
extern "C" void kernel_launch(void* const* d_in, const int* in_sizes, int n_in,
                              void* d_out, int out_size)
{
    const float* ta   = (const float*)d_in[0];
    const float* tb   = (const float*)d_in[1];
    const float* W1   = (const float*)d_in[2];
    const float* b1   = (const float*)d_in[3];
    const float* W2   = (const float*)d_in[4];
    const float* b2   = (const float*)d_in[5];
    const float* W3   = (const float*)d_in[6];
    const float* b3   = (const float*)d_in[7];
    const float* W4   = (const float*)d_in[8];
    const float* b4   = (const float*)d_in[9];
    const float* w_r1 = (const float*)d_in[10];
    float* out = (float*)d_out;

    dim3 gProj(DD / 256, NS / 128);      // 4 x 64
    dim3 gSim(32, NTILE);                // 32 x 64 (sym self-prunes)
    int  zb  = (NS + 255) / 256;
    int  cbA = (NS*DD/4 + 255) / 256;
    int  cbW = (DD*DD/4 + 255) / 256;

    conv_W1<<<cbW, 256>>>(W1);
    conv_W2<<<cbW, 256>>>(W2);
    conv_W3<<<cbW, 256>>>(W3);
    conv_W4<<<cbW, 256>>>(W4);
    zero_stats<<<zb, 256>>>(1);

    conv_A1<<<cbA, 256>>>(ta);
    conv_A2<<<cbA, 256>>>(tb);
    g_A1W1U1<<<gProj, 256>>>(b1);
    g_A2W1U2<<<gProj, 256>>>(b1);
    g_U1W2H1<<<gProj, 256>>>(b2);
    g_U2W2H2<<<gProj, 256>>>(b2);
    norm_H1<<<NS, 256>>>();
    norm_H2<<<NS, 256>>>();
    sim_H1_sym<<<gSim, 256>>>();
    sim_H2_sym<<<gSim, 256>>>();
    sim_H_full<<<gSim, 256>>>();
    loss_reduce<<<zb, 256>>>(0);

    trans_A1<<<NS, 256>>>(ta);
    trans_A2<<<NS, 256>>>(tb);
    zero_stats<<<zb, 256>>>(0);
    g_A1W3U1<<<gProj, 256>>>(b3);
    g_A2W3U2<<<gProj, 256>>>(b3);
    g_U1W4H1<<<gProj, 256>>>(b4);
    g_U2W4H2<<<gProj, 256>>>(b4);
    norm_H1<<<NS, 256>>>();
    norm_H2<<<NS, 256>>>();
    sim_H1_sym<<<gSim, 256>>>();
    sim_H2_sym<<<gSim, 256>>>();
    sim_H_full<<<gSim, 256>>>();
    loss_reduce<<<zb, 256>>>(1);

    finalize_k<<<1, 1>>>(w_r1, out);
}